// round 5
// baseline (speedup 1.0000x reference)
#include <cuda_runtime.h>

// GRU seq2seq forecaster — packed f32x2 (FFMA2) version.
//  K1: gi[t,b,192] = x[b,t,:] @ enc_Wih^T + biases, 2 positions packed per lane
//  K2: recurrence. Lane-pair (u, kh): unit u, k-half kh. Whh duplicated-packed
//      in 192 regs; two batch rows packed per lane; shfl.xor(1) k-reduction.

#define B_    4096
#define TIN   168
#define C_    32
#define H_    64
#define TOUT  24
#define G3    192

typedef unsigned long long u64;

__device__ float g_gi[(size_t)TIN * B_ * G3];   // 528 MB scratch

__device__ __forceinline__ u64 pack2(float a, float b) {
    u64 d;
    asm("mov.b64 %0, {%1, %2};" : "=l"(d) : "r"(__float_as_uint(a)), "r"(__float_as_uint(b)));
    return d;
}
__device__ __forceinline__ void unpack2(u64 v, float& a, float& b) {
    unsigned lo, hi;
    asm("mov.b64 {%0, %1}, %2;" : "=r"(lo), "=r"(hi) : "l"(v));
    a = __uint_as_float(lo); b = __uint_as_float(hi);
}
__device__ __forceinline__ u64 dup2(float v) { return pack2(v, v); }
__device__ __forceinline__ u64 ffma2(u64 a, u64 b, u64 c) {
    u64 d; asm("fma.rn.f32x2 %0, %1, %2, %3;" : "=l"(d) : "l"(a), "l"(b), "l"(c)); return d;
}
__device__ __forceinline__ u64 fadd2(u64 a, u64 b) {
    u64 d; asm("add.rn.f32x2 %0, %1, %2;" : "=l"(d) : "l"(a), "l"(b)); return d;
}
// Combine k-halves across the lane pair: one shfl per accumulator.
// acc = (rowA_partial, rowB_partial) for THIS thread's k-half.
// Returns full sum for THIS thread's row (kh=0 -> rowA, kh=1 -> rowB).
__device__ __forceinline__ float redpair(u64 acc, int kh) {
    float lo, hi; unpack2(acc, lo, hi);
    float mine = kh ? hi : lo;
    float send = kh ? lo : hi;      // the half the partner's row needs
    return mine + __shfl_xor_sync(0xFFFFFFFFu, send, 1);
}
__device__ __forceinline__ float fsig(float a) {
    return __fdividef(1.0f, 1.0f + __expf(-a));
}
__device__ __forceinline__ float ftanh(float a) {
    float e = __expf(2.0f * a);
    return 1.0f - __fdividef(2.0f, e + 1.0f);
}

// ============================ kernel 1: gi precompute ============================
#define K1_TH   192
#define K1_P    16            // positions per iter (8 packed pairs)
#define K1_GRID 1184

__global__ __launch_bounds__(K1_TH)
void gi_kernel(const float* __restrict__ x, const float* __restrict__ eWih,
               const float* __restrict__ eBih, const float* __restrict__ eBhh)
{
    __shared__ __align__(16) float sX2[(K1_P / 2) * 64];   // packed (posA,posB) per c
    const int o = threadIdx.x;                             // gate-row 0..191
    u64 w2[32];
#pragma unroll
    for (int c = 0; c < 32; c++) w2[c] = dup2(eWih[o * 32 + c]);
    const float bo = eBih[o] + ((o < 2 * H_) ? eBhh[o] : 0.0f);   // fold bhh for r,z

    const int nIter = (TIN * B_) / K1_P;
    for (int it = blockIdx.x; it < nIter; it += gridDim.x) {
        const int P = it * K1_P;
        __syncthreads();
        for (int idx = o; idx < K1_P * C_; idx += K1_TH) {
            const int pl = idx >> 5, c = idx & 31;
            const int p = P + pl;
            const int b = p & (B_ - 1), tt = p >> 12;
            sX2[(pl >> 1) * 64 + c * 2 + (pl & 1)] = x[((size_t)b * TIN + tt) * C_ + c];
        }
        __syncthreads();
#pragma unroll
        for (int pl2 = 0; pl2 < K1_P / 2; pl2++) {
            const ulonglong2* xv = reinterpret_cast<const ulonglong2*>(sX2 + pl2 * 64);
            u64 acc0 = dup2(bo), acc1 = dup2(0.0f);
#pragma unroll
            for (int q = 0; q < 16; q++) {
                ulonglong2 v = xv[q];               // broadcast LDS
                acc0 = ffma2(w2[2 * q],     v.x, acc0);
                acc1 = ffma2(w2[2 * q + 1], v.y, acc1);
            }
            float a, b2; unpack2(fadd2(acc0, acc1), a, b2);
            const size_t base = (size_t)(P + 2 * pl2) * G3 + o;
            g_gi[base]      = a;                    // even position
            g_gi[base + G3] = b2;                   // odd position
        }
    }
}

// ============================ kernel 2: recurrence ============================
#define NG2   2                 // groups per CTA (128 threads each)
#define CTA2  256
#define GRID2 148
#define RPG   14                // rows per group (7 packed pairs); 148*2*14=4144>=4096
#define NP    (RPG / 2)         // 7 pairs

// shared float offsets
#define SH_HP   0                                   // hp[2g][2par][NP*128]
#define HP_G    (2 * NP * 128)                      // 1792 per group
#define SH_PV   (SH_HP + NG2 * HP_G)                // 3584
#define PV_G    (2 * NP * 64)                       // 896 per group
#define SH_DW   (SH_PV + NG2 * PV_G)                // 5376 ; dWih dup-packed, stride 34 u64
#define DW_FL   (G3 * 34 * 2)                       // 13056
#define SH_PWT  (SH_DW + DW_FL)                     // 18432 ; projW dup-packed, stride 66 u64
#define PW_FL   (C_ * 66 * 2)                       // 4224
#define SH_SB   (SH_PWT + PW_FL)                    // 22656
#define SB_FL   (4 * 64 + 32)
#define SM2_FLOATS (SH_SB + SB_FL)                  // 22944
#define SM2_BYTES  (SM2_FLOATS * 4)

__global__ __launch_bounds__(CTA2, 1)
void gru_rec_kernel(const float* __restrict__ x,
                    const float* __restrict__ eWhh, const float* __restrict__ eBhh,
                    const float* __restrict__ dWih, const float* __restrict__ dWhh,
                    const float* __restrict__ dBih, const float* __restrict__ dBhh,
                    const float* __restrict__ pW,   const float* __restrict__ pB,
                    float* __restrict__ out)
{
    extern __shared__ __align__(16) float sm[];
    u64* sDW2u = reinterpret_cast<u64*>(sm + SH_DW);
    u64* sPW2u = reinterpret_cast<u64*>(sm + SH_PWT);
    float* sb  = sm + SH_SB;

    const int tid = threadIdx.x;
    const int g  = tid >> 7;         // group 0..1
    const int lt = tid & 127;        // thread in group
    const int u  = lt >> 1;          // hidden unit 0..63
    const int kh = lt & 1;           // k-half

    // ---- stage decoder constants (dup-packed) ----
    for (int i = tid; i < G3 * C_; i += CTA2)
        sDW2u[(i >> 5) * 34 + (i & 31)] = dup2(dWih[i]);
    for (int i = tid; i < C_ * H_; i += CTA2)
        sPW2u[(i >> 6) * 66 + (i & 63)] = dup2(pW[i]);
    if (tid < 64) {
        sb[tid]       = dBih[tid]      + dBhh[tid];
        sb[64 + tid]  = dBih[64 + tid] + dBhh[64 + tid];
        sb[128 + tid] = dBih[128 + tid];
        sb[192 + tid] = dBhh[128 + tid];
    }
    if (tid < 32) sb[256 + tid] = pB[tid];

    float* hpG = sm + SH_HP + g * HP_G;     // [2 par][NP*128]
    float* pvG = sm + SH_PV + g * PV_G;     // [2 par][NP*64]
    for (int i = lt; i < NP * 128; i += 128) hpG[i] = 0.0f;   // h0 = 0 (parity 0)

    // ---- encoder Whh, duplicated-packed, this thread's k-half: 192 regs ----
    u64 wr2[32], wz2[32], wn2[32];
#pragma unroll
    for (int q = 0; q < 32; q++) {
        wr2[q] = dup2(eWhh[(      u) * 64 + kh * 32 + q]);
        wz2[q] = dup2(eWhh[( 64 + u) * 64 + kh * 32 + q]);
        wn2[q] = dup2(eWhh[(128 + u) * 64 + kh * 32 + q]);
    }
    const float bhn = eBhh[128 + u];

    __syncthreads();

    const int rowbase = (blockIdx.x * NG2 + g) * RPG;
    int par = 0;

    // ======================= encoder: 168 steps =======================
    for (int t = 0; t < TIN; t++) {
        const float* gsrc = g_gi + (size_t)t * (B_ * G3);
        const float* hR = hpG + par * (NP * 128);
        float* hW = hpG + (par ^ 1) * (NP * 128);

        int r0 = min(rowbase + kh, B_ - 1);
        float gr = gsrc[r0 * G3 + u];
        float gz = gsrc[r0 * G3 + 64 + u];
        float gn = gsrc[r0 * G3 + 128 + u];

#pragma unroll 1
        for (int p = 0; p < NP; p++) {
            const int rn = min(rowbase + 2 * (p + 1) + kh, B_ - 1);   // prefetch (clamped)
            const float grn = gsrc[rn * G3 + u];
            const float gzn = gsrc[rn * G3 + 64 + u];
            const float gnn = gsrc[rn * G3 + 128 + u];

            u64 ar0 = 0, ar1 = 0, az0 = 0, az1 = 0, ah0 = 0, ah1 = 0;
            const ulonglong2* hv = reinterpret_cast<const ulonglong2*>(hR + p * 128 + kh * 64);
#pragma unroll
            for (int q = 0; q < 16; q++) {
                ulonglong2 v = hv[q];
                ar0 = ffma2(wr2[2*q],   v.x, ar0); az0 = ffma2(wz2[2*q],   v.x, az0);
                ah0 = ffma2(wn2[2*q],   v.x, ah0);
                ar1 = ffma2(wr2[2*q+1], v.y, ar1); az1 = ffma2(wz2[2*q+1], v.y, az1);
                ah1 = ffma2(wn2[2*q+1], v.y, ah1);
            }
            const float arF = redpair(fadd2(ar0, ar1), kh);
            const float azF = redpair(fadd2(az0, az1), kh);
            const float ahF = redpair(fadd2(ah0, ah1), kh);
            const float hold = hR[p * 128 + 2 * u + kh];
            const float rg = fsig(arF + gr), zg = fsig(azF + gz);
            const float nn = ftanh(fmaf(rg, ahF + bhn, gn));
            hW[p * 128 + 2 * u + kh] = (1.0f - zg) * nn + zg * hold;
            gr = grn; gz = gzn; gn = gnn;
        }
        asm volatile("bar.sync %0, %1;" :: "r"(2 + g), "r"(128) : "memory");
        par ^= 1;
    }

    // ======================= decoder: 24 steps =======================
#pragma unroll
    for (int q = 0; q < 32; q++) {
        wr2[q] = dup2(dWhh[(      u) * 64 + kh * 32 + q]);
        wz2[q] = dup2(dWhh[( 64 + u) * 64 + kh * 32 + q]);
        wn2[q] = dup2(dWhh[(128 + u) * 64 + kh * 32 + q]);
    }
    const float dbr = sb[u], dbz = sb[64 + u], dbni = sb[128 + u], dbnh = sb[192 + u];

    {   // prev_0 = x[:, TIN-1, :] packed (rowA,rowB)
        const int c = lt & 31;
        for (int p = lt >> 5; p < NP; p += 4) {
            const int rA = min(rowbase + 2 * p,     B_ - 1);
            const int rB = min(rowbase + 2 * p + 1, B_ - 1);
            const float a  = x[((size_t)rA * TIN + (TIN - 1)) * C_ + c];
            const float b2 = x[((size_t)rB * TIN + (TIN - 1)) * C_ + c];
            reinterpret_cast<u64*>(pvG + p * 64)[c] = pack2(a, b2);
        }
    }
    asm volatile("bar.sync %0, %1;" :: "r"(2 + g), "r"(128) : "memory");

    int ppar = 0;
    for (int t = 0; t < TOUT; t++) {
        const float* hR = hpG + par * (NP * 128);
        float* hW = hpG + (par ^ 1) * (NP * 128);
        const float* pvR = pvG + ppar * (NP * 64);
        float* pvN = pvG + (ppar ^ 1) * (NP * 64);

#pragma unroll 1
        for (int p = 0; p < NP; p++) {
            u64 ar2 = 0, az2 = 0, an2 = 0, aha = 0, ahb = 0;
            // Wih @ prev (this thread's c-half: 16 channels)
            const ulonglong2* pvv = reinterpret_cast<const ulonglong2*>(pvR + p * 64 + kh * 32);
            const ulonglong2* wiR = reinterpret_cast<const ulonglong2*>(sDW2u + (      u) * 34 + kh * 16);
            const ulonglong2* wiZ = reinterpret_cast<const ulonglong2*>(sDW2u + ( 64 + u) * 34 + kh * 16);
            const ulonglong2* wiN = reinterpret_cast<const ulonglong2*>(sDW2u + (128 + u) * 34 + kh * 16);
#pragma unroll
            for (int q = 0; q < 8; q++) {
                ulonglong2 v = pvv[q];
                ulonglong2 a = wiR[q], b = wiZ[q], c = wiN[q];
                ar2 = ffma2(a.x, v.x, ar2); ar2 = ffma2(a.y, v.y, ar2);
                az2 = ffma2(b.x, v.x, az2); az2 = ffma2(b.y, v.y, az2);
                an2 = ffma2(c.x, v.x, an2); an2 = ffma2(c.y, v.y, an2);
            }
            // Whh @ h
            const ulonglong2* hv = reinterpret_cast<const ulonglong2*>(hR + p * 128 + kh * 64);
#pragma unroll
            for (int q = 0; q < 16; q++) {
                ulonglong2 v = hv[q];
                ar2 = ffma2(wr2[2*q],   v.x, ar2); az2 = ffma2(wz2[2*q],   v.x, az2);
                aha = ffma2(wn2[2*q],   v.x, aha);
                ar2 = ffma2(wr2[2*q+1], v.y, ar2); az2 = ffma2(wz2[2*q+1], v.y, az2);
                ahb = ffma2(wn2[2*q+1], v.y, ahb);
            }
            const float arF = redpair(ar2, kh) + dbr;
            const float azF = redpair(az2, kh) + dbz;
            const float anF = redpair(an2, kh) + dbni;
            const float ahF = redpair(fadd2(aha, ahb), kh) + dbnh;
            const float hold = hR[p * 128 + 2 * u + kh];
            const float rg = fsig(arF), zg = fsig(azF);
            const float nn = ftanh(fmaf(rg, ahF, anF));
            hW[p * 128 + 2 * u + kh] = (1.0f - zg) * nn + zg * hold;
        }
        asm volatile("bar.sync %0, %1;" :: "r"(2 + g), "r"(128) : "memory");

        // projection + next decoder input: thread -> (channel c, pair subset)
        {
            const int c = lt & 31;
            const u64 pbc = dup2(sb[256 + c]);
            const ulonglong2* wv = reinterpret_cast<const ulonglong2*>(sPW2u + c * 66);
            for (int p = lt >> 5; p < NP; p += 4) {
                const ulonglong2* hv = reinterpret_cast<const ulonglong2*>(hW + p * 128);
                u64 a0 = pbc, a1 = dup2(0.0f);
#pragma unroll
                for (int q = 0; q < 32; q++) {
                    ulonglong2 w = wv[q];
                    ulonglong2 h = hv[q];            // broadcast (warp shares p)
                    a0 = ffma2(w.x, h.x, a0);
                    a1 = ffma2(w.y, h.y, a1);
                }
                const u64 pred = fadd2(a0, a1);
                reinterpret_cast<u64*>(pvN + p * 64)[c] = pred;
                float pa, pb2; unpack2(pred, pa, pb2);
                const int rA = rowbase + 2 * p, rB = rA + 1;
                if (rA < B_) out[((size_t)rA * TOUT + t) * C_ + c] = pa;
                if (rB < B_) out[((size_t)rB * TOUT + t) * C_ + c] = pb2;
            }
        }
        asm volatile("bar.sync %0, %1;" :: "r"(2 + g), "r"(128) : "memory");
        par ^= 1; ppar ^= 1;
    }
}

// ============================ launch ============================
extern "C" void kernel_launch(void* const* d_in, const int* in_sizes, int n_in,
                              void* d_out, int out_size)
{
    (void)in_sizes; (void)n_in; (void)out_size;
    const float* x    = (const float*)d_in[0];
    const float* eWih = (const float*)d_in[1];
    const float* eWhh = (const float*)d_in[2];
    const float* eBih = (const float*)d_in[3];
    const float* eBhh = (const float*)d_in[4];
    const float* dWih = (const float*)d_in[5];
    const float* dWhh = (const float*)d_in[6];
    const float* dBih = (const float*)d_in[7];
    const float* dBhh = (const float*)d_in[8];
    const float* pW   = (const float*)d_in[9];
    const float* pB   = (const float*)d_in[10];
    float* out = (float*)d_out;

    gi_kernel<<<K1_GRID, K1_TH>>>(x, eWih, eBih, eBhh);

    cudaFuncSetAttribute(gru_rec_kernel,
                         cudaFuncAttributeMaxDynamicSharedMemorySize, SM2_BYTES);
    gru_rec_kernel<<<GRID2, CTA2, SM2_BYTES>>>(
        x, eWhh, eBhh, dWih, dWhh, dBih, dBhh, pW, pB, out);
}

// round 7
// speedup vs baseline: 1.2936x; 1.2936x over previous
#include <cuda_runtime.h>
#include <cuda_bf16.h>
#include <cstdint>

// GRU seq2seq forecaster.
//  K1 (tensor): gi[t,b,192] = x[b,t,:] @ enc_Wih^T + biases via warp-level
//               mma.sync bf16 (sm_80+ PTX, works on plain sm_100 target),
//               split-K: xh*Wh + xl*Wh + xh*Wl (xl*Wl dropped, ~2^-16 rel).
//  K2 (SIMT):   persistent recurrence, thread = hidden unit, Whh in registers,
//               h broadcast from double-buffered SMEM (proven R3 design, 719us).

#define B_    4096
#define TIN   168
#define C_    32
#define H_    64
#define TOUT  24
#define G3    192

__device__ float g_gi[(size_t)TIN * B_ * G3];   // 528 MB scratch

// ============================ kernel 1: gi via mma.sync ============================
// Per CTA: one (t, 128-row) tile. 8 warps, each an m16 slice x all N=192.
#define AS 72     // sA row stride (bf16): 64 data + 8 pad -> conflict-free frag LDS
#define WS 72     // sW row stride

__global__ __launch_bounds__(256)
void gi_mma_kernel(const float* __restrict__ x, const float* __restrict__ eWih,
                   const float* __restrict__ eBih, const float* __restrict__ eBhh)
{
    __shared__ __nv_bfloat16 sA[128 * AS];   // [row][0:32)=xh, [32:64)=xl
    __shared__ __nv_bfloat16 sW[192 * WS];   // [o]  [0:32)=Wh, [32:64)=Wl
    __shared__ float sBias[192];

    const int tid  = threadIdx.x;
    const int wid  = tid >> 5;
    const int lane = tid & 31;
    const int t  = blockIdx.x >> 5;          // 0..167
    const int b0 = (blockIdx.x & 31) * 128;  // 0..3968

    // ---- stage W hi/lo + bias ----
    for (int i = tid; i < 192 * 32; i += 256) {
        const int o = i >> 5, c = i & 31;
        const float v = eWih[i];
        const __nv_bfloat16 hi = __float2bfloat16(v);
        const __nv_bfloat16 lo = __float2bfloat16(v - __bfloat162float(hi));
        sW[o * WS + c]      = hi;
        sW[o * WS + 32 + c] = lo;
    }
    for (int o = tid; o < 192; o += 256)
        sBias[o] = eBih[o] + ((o < 128) ? eBhh[o] : 0.0f);   // fold bhh for r,z

    // ---- stage A hi/lo (row = batch row in tile; coalesced 128B per warp-row) ----
    for (int i = tid; i < 128 * 32; i += 256) {
        const int r = i >> 5, c = i & 31;
        const float v = x[((size_t)(b0 + r) * TIN + t) * C_ + c];
        const __nv_bfloat16 hi = __float2bfloat16(v);
        const __nv_bfloat16 lo = __float2bfloat16(v - __bfloat162float(hi));
        sA[r * AS + c]      = hi;
        sA[r * AS + 32 + c] = lo;
    }
    __syncthreads();

    const int g  = lane >> 2;      // group-of-4 id (0..7)
    const int tg = lane & 3;       // thread-in-group
    const int m0 = wid * 16;       // this warp's row slice

    float acc[24][4];
#pragma unroll
    for (int nt = 0; nt < 24; nt++) {
        acc[nt][0] = 0.f; acc[nt][1] = 0.f; acc[nt][2] = 0.f; acc[nt][3] = 0.f;
    }

    // 6 k-steps of 16: (A-chunk, B-chunk) column bases selecting the 3 products
    const int ACB[6] = {0, 16, 32, 48, 0, 16};   // xh,xh, xl,xl, xh,xh
    const int BCB[6] = {0, 16, 0, 16, 32, 48};   // Wh,Wh, Wh,Wh, Wl,Wl

#pragma unroll
    for (int ks = 0; ks < 6; ks++) {
        const int ac = ACB[ks], bc = BCB[ks];
        const uint32_t a0 = *reinterpret_cast<const uint32_t*>(&sA[(m0 + g)     * AS + ac + 2 * tg]);
        const uint32_t a1 = *reinterpret_cast<const uint32_t*>(&sA[(m0 + g + 8) * AS + ac + 2 * tg]);
        const uint32_t a2 = *reinterpret_cast<const uint32_t*>(&sA[(m0 + g)     * AS + ac + 2 * tg + 8]);
        const uint32_t a3 = *reinterpret_cast<const uint32_t*>(&sA[(m0 + g + 8) * AS + ac + 2 * tg + 8]);
#pragma unroll
        for (int nt = 0; nt < 24; nt++) {
            const int n = nt * 8 + g;   // B frag col(n) = groupID
            const uint32_t br0 = *reinterpret_cast<const uint32_t*>(&sW[n * WS + bc + 2 * tg]);
            const uint32_t br1 = *reinterpret_cast<const uint32_t*>(&sW[n * WS + bc + 2 * tg + 8]);
            asm volatile(
                "mma.sync.aligned.m16n8k16.row.col.f32.bf16.bf16.f32 "
                "{%0,%1,%2,%3}, {%4,%5,%6,%7}, {%8,%9}, {%0,%1,%2,%3};"
                : "+f"(acc[nt][0]), "+f"(acc[nt][1]), "+f"(acc[nt][2]), "+f"(acc[nt][3])
                : "r"(a0), "r"(a1), "r"(a2), "r"(a3), "r"(br0), "r"(br1));
        }
    }

    // ---- epilogue: +bias, store. Lane covers rows m0+g / m0+g+8, cols n0+2tg,+1 ----
    {
        const int row0 = b0 + m0 + g;
        float* d0 = g_gi + ((size_t)t * B_ + row0) * G3;
        float* d1 = d0 + 8 * G3;                 // row +8
#pragma unroll
        for (int nt = 0; nt < 24; nt++) {
            const int col = nt * 8 + 2 * tg;
            const float bi0 = sBias[col], bi1 = sBias[col + 1];
            float2 v0 = make_float2(acc[nt][0] + bi0, acc[nt][1] + bi1);
            float2 v1 = make_float2(acc[nt][2] + bi0, acc[nt][3] + bi1);
            *reinterpret_cast<float2*>(d0 + col) = v0;
            *reinterpret_cast<float2*>(d1 + col) = v1;
        }
    }
}

// ============================ kernel 2: recurrence (R3, proven) ============================
__device__ __forceinline__ float fsig(float a) {
    return __fdividef(1.0f, 1.0f + __expf(-a));
}
__device__ __forceinline__ float ftanh(float a) {
    float e = __expf(2.0f * a);
    return 1.0f - __fdividef(2.0f, e + 1.0f);
}
#define FMA4(acc, w4, h4) \
    acc = fmaf((w4).x, (h4).x, acc); acc = fmaf((w4).y, (h4).y, acc); \
    acc = fmaf((w4).z, (h4).z, acc); acc = fmaf((w4).w, (h4).w, acc);

#define NG    4
#define CTA2  256
#define GRID2 148
#define RPG   7
#define DW_S  33
#define PW_S  68

#define SH_HBUF 0
#define HBUF_SZ (2 * NG * RPG * 64)
#define SH_PREV (SH_HBUF + HBUF_SZ)
#define PREV_SZ (2 * NG * RPG * 32)
#define SH_DWIH (SH_PREV + PREV_SZ)
#define DWIH_SZ (G3 * DW_S)
#define SH_PW   (SH_DWIH + DWIH_SZ)
#define PW_SZ   (C_ * PW_S)
#define SH_DB   (SH_PW + PW_SZ)
#define DB_SZ   (4 * 64 + 32)
#define SM2_FLOATS (SH_DB + DB_SZ)
#define SM2_BYTES  (SM2_FLOATS * 4)

__global__ __launch_bounds__(CTA2, 1)
void gru_rec_kernel(const float* __restrict__ x,
                    const float* __restrict__ eWhh, const float* __restrict__ eBhh,
                    const float* __restrict__ dWih, const float* __restrict__ dWhh,
                    const float* __restrict__ dBih, const float* __restrict__ dBhh,
                    const float* __restrict__ pW,   const float* __restrict__ pB,
                    float* __restrict__ out)
{
    extern __shared__ float sm[];
    const int tid = threadIdx.x;
    const int g = tid >> 6;
    const int u = tid & 63;

    for (int i = tid; i < G3 * C_; i += CTA2)
        sm[SH_DWIH + (i >> 5) * DW_S + (i & 31)] = dWih[i];
    for (int i = tid; i < C_ * H_; i += CTA2)
        sm[SH_PW + (i >> 6) * PW_S + (i & 63)] = pW[i];
    if (tid < 64) {
        sm[SH_DB + tid]       = dBih[tid]      + dBhh[tid];
        sm[SH_DB + 64 + tid]  = dBih[64 + tid] + dBhh[64 + tid];
        sm[SH_DB + 128 + tid] = dBih[128 + tid];
        sm[SH_DB + 192 + tid] = dBhh[128 + tid];
    }
    if (tid < 32) sm[SH_DB + 256 + tid] = pB[tid];

    float* hbufG = sm + SH_HBUF + g * (RPG * 64);
    float* prevG = sm + SH_PREV + g * (RPG * 32);
    const int HP = NG * RPG * 64;
    const int PP = NG * RPG * 32;
#pragma unroll
    for (int i = 0; i < RPG; i++) hbufG[i * 64 + u] = 0.0f;

    float4 wr[16], wz[16], wn[16];
#pragma unroll
    for (int q = 0; q < 16; q++) {
        wr[q] = reinterpret_cast<const float4*>(eWhh)[(      u) * 16 + q];
        wz[q] = reinterpret_cast<const float4*>(eWhh)[( 64 + u) * 16 + q];
        wn[q] = reinterpret_cast<const float4*>(eWhh)[(128 + u) * 16 + q];
    }
    float bhn = eBhh[128 + u];

    __syncthreads();

    const int rowbase = (blockIdx.x * NG + g) * RPG;
    int par = 0;

    for (int t = 0; t < TIN; t++) {
        const float* gsrc = g_gi + (size_t)t * (B_ * G3) + u;
        const float* hR = hbufG + par * HP;
        float* hW = hbufG + (par ^ 1) * HP;

        int r0 = min(rowbase + 0, B_ - 1) * G3;
        int r1 = min(rowbase + 1, B_ - 1) * G3;
        float grA = gsrc[r0], gzA = gsrc[r0 + 64], gnA = gsrc[r0 + 128];
        float grB = gsrc[r1], gzB = gsrc[r1 + 64], gnB = gsrc[r1 + 128];

#pragma unroll 1
        for (int pi = 0; pi < RPG - 1; pi += 2) {
            const int rC = min(rowbase + pi + 2, B_ - 1) * G3;
            const int rD = min(rowbase + pi + 3, B_ - 1) * G3;
            const float grC = gsrc[rC], gzC = gsrc[rC + 64], gnC = gsrc[rC + 128];
            const float grD = gsrc[rD], gzD = gsrc[rD + 64], gnD = gsrc[rD + 128];

            const float4* hA = reinterpret_cast<const float4*>(hR + pi * 64);
            const float4* hB = reinterpret_cast<const float4*>(hR + (pi + 1) * 64);
            float arA = 0.f, azA = 0.f, ahA = 0.f;
            float arB = 0.f, azB = 0.f, ahB = 0.f;
#pragma unroll
            for (int q = 0; q < 16; q++) {
                const float4 a = hA[q], b = hB[q];
                FMA4(arA, wr[q], a); FMA4(azA, wz[q], a); FMA4(ahA, wn[q], a);
                FMA4(arB, wr[q], b); FMA4(azB, wz[q], b); FMA4(ahB, wn[q], b);
            }
            const float holdA = hR[pi * 64 + u];
            const float holdB = hR[(pi + 1) * 64 + u];
            const float rgA = fsig(arA + grA), zgA = fsig(azA + gzA);
            const float nA  = ftanh(fmaf(rgA, ahA + bhn, gnA));
            const float hnA = (1.0f - zgA) * nA + zgA * holdA;
            const float rgB = fsig(arB + grB), zgB = fsig(azB + gzB);
            const float nB  = ftanh(fmaf(rgB, ahB + bhn, gnB));
            const float hnB = (1.0f - zgB) * nB + zgB * holdB;
            hW[pi * 64 + u] = hnA;
            hW[(pi + 1) * 64 + u] = hnB;

            grA = grC; gzA = gzC; gnA = gnC;
            grB = grD; gzB = gzD; gnB = gnD;
        }
        {
            const int i6 = RPG - 1;
            const float4* hA = reinterpret_cast<const float4*>(hR + i6 * 64);
            float arA = 0.f, azA = 0.f, ahA = 0.f;
#pragma unroll
            for (int q = 0; q < 16; q++) {
                const float4 a = hA[q];
                FMA4(arA, wr[q], a); FMA4(azA, wz[q], a); FMA4(ahA, wn[q], a);
            }
            const float holdA = hR[i6 * 64 + u];
            const float rgA = fsig(arA + grA), zgA = fsig(azA + gzA);
            const float nA  = ftanh(fmaf(rgA, ahA + bhn, gnA));
            hW[i6 * 64 + u] = (1.0f - zgA) * nA + zgA * holdA;
        }
        asm volatile("bar.sync %0, %1;" :: "r"(g), "r"(64) : "memory");
        par ^= 1;
    }

#pragma unroll
    for (int q = 0; q < 16; q++) {
        wr[q] = reinterpret_cast<const float4*>(dWhh)[(      u) * 16 + q];
        wz[q] = reinterpret_cast<const float4*>(dWhh)[( 64 + u) * 16 + q];
        wn[q] = reinterpret_cast<const float4*>(dWhh)[(128 + u) * 16 + q];
    }
    const float dbr  = sm[SH_DB + u],        dbz  = sm[SH_DB + 64 + u];
    const float dbni = sm[SH_DB + 128 + u],  dbnh = sm[SH_DB + 192 + u];

    if (u < 32) {
#pragma unroll 1
        for (int i = 0; i < RPG; i++) {
            const int r = min(rowbase + i, B_ - 1);
            prevG[i * 32 + u] = x[((size_t)r * TIN + (TIN - 1)) * C_ + u];
        }
    }
    asm volatile("bar.sync %0, %1;" :: "r"(g), "r"(64) : "memory");

    int ppar = 0;
    for (int t = 0; t < TOUT; t++) {
        const float* hR = hbufG + par * HP;
        float* hW = hbufG + (par ^ 1) * HP;
        const float* pv = prevG + ppar * PP;
        float* pvN = prevG + (ppar ^ 1) * PP;

#pragma unroll 1
        for (int i = 0; i < RPG; i++) {
            float ar = dbr, az = dbz, ani = dbni, ah = dbnh;
            const float4* p4p = reinterpret_cast<const float4*>(pv + i * 32);
#pragma unroll
            for (int q = 0; q < 8; q++) {
                const float4 p4 = p4p[q];
                const float* wir = sm + SH_DWIH + (      u) * DW_S + 4 * q;
                const float* wiz = sm + SH_DWIH + ( 64 + u) * DW_S + 4 * q;
                const float* win = sm + SH_DWIH + (128 + u) * DW_S + 4 * q;
                ar  = fmaf(wir[0], p4.x, ar);  ar  = fmaf(wir[1], p4.y, ar);
                ar  = fmaf(wir[2], p4.z, ar);  ar  = fmaf(wir[3], p4.w, ar);
                az  = fmaf(wiz[0], p4.x, az);  az  = fmaf(wiz[1], p4.y, az);
                az  = fmaf(wiz[2], p4.z, az);  az  = fmaf(wiz[3], p4.w, az);
                ani = fmaf(win[0], p4.x, ani); ani = fmaf(win[1], p4.y, ani);
                ani = fmaf(win[2], p4.z, ani); ani = fmaf(win[3], p4.w, ani);
            }
            const float4* hA = reinterpret_cast<const float4*>(hR + i * 64);
#pragma unroll
            for (int q = 0; q < 16; q++) {
                const float4 a = hA[q];
                FMA4(ar, wr[q], a); FMA4(az, wz[q], a); FMA4(ah, wn[q], a);
            }
            const float rg = fsig(ar), zg = fsig(az);
            const float nn = ftanh(fmaf(rg, ah, ani));
            const float hold = hR[i * 64 + u];
            hW[i * 64 + u] = (1.0f - zg) * nn + zg * hold;
        }
        asm volatile("bar.sync %0, %1;" :: "r"(g), "r"(64) : "memory");

        if (u < 32) {
#pragma unroll 1
            for (int i = 0; i < RPG; i++) {
                const float4* h4 = reinterpret_cast<const float4*>(hW + i * 64);
                float p = sm[SH_DB + 256 + u];
#pragma unroll
                for (int q = 0; q < 16; q++) {
                    const float4 hh = h4[q];
                    const float4 w4 = *reinterpret_cast<const float4*>(sm + SH_PW + u * PW_S + 4 * q);
                    FMA4(p, w4, hh);
                }
                pvN[i * 32 + u] = p;
                const int r = min(rowbase + i, B_ - 1);
                out[((size_t)r * TOUT + t) * C_ + u] = p;
            }
        }
        asm volatile("bar.sync %0, %1;" :: "r"(g), "r"(64) : "memory");
        par ^= 1; ppar ^= 1;
    }
}

// ============================ launch ============================
extern "C" void kernel_launch(void* const* d_in, const int* in_sizes, int n_in,
                              void* d_out, int out_size)
{
    (void)in_sizes; (void)n_in; (void)out_size;
    const float* x    = (const float*)d_in[0];
    const float* eWih = (const float*)d_in[1];
    const float* eWhh = (const float*)d_in[2];
    const float* eBih = (const float*)d_in[3];
    const float* eBhh = (const float*)d_in[4];
    const float* dWih = (const float*)d_in[5];
    const float* dWhh = (const float*)d_in[6];
    const float* dBih = (const float*)d_in[7];
    const float* dBhh = (const float*)d_in[8];
    const float* pW   = (const float*)d_in[9];
    const float* pB   = (const float*)d_in[10];
    float* out = (float*)d_out;

    gi_mma_kernel<<<TIN * 32, 256>>>(x, eWih, eBih, eBhh);

    cudaFuncSetAttribute(gru_rec_kernel,
                         cudaFuncAttributeMaxDynamicSharedMemorySize, SM2_BYTES);
    gru_rec_kernel<<<GRID2, CTA2, SM2_BYTES>>>(
        x, eWhh, eBhh, dWih, dWhh, dBih, dBhh, pW, pB, out);
}

// round 8
// speedup vs baseline: 2.4319x; 1.8799x over previous
#include <cuda_runtime.h>
#include <cuda_bf16.h>
#include <cstdint>

// GRU seq2seq forecaster — tensor-core recurrence.
//  K1: gi = x@Wih^T + biases via mma.sync bf16 split (proven R6), 4 tiles/CTA.
//  K2: recurrence via mma.sync: Whh split hi/lo as register-stationary B-frags,
//      h as bf16-split A-frags in double-buffered SMEM, fp32 h in registers.
//      Permuted output columns so each lane owns r,z,n of the same 4 units.

#define B_    4096
#define TIN   168
#define C_    32
#define H_    64
#define TOUT  24
#define G3    192

typedef uint32_t u32;

__device__ float g_gi[(size_t)TIN * B_ * G3];   // 528 MB scratch

__device__ __forceinline__ float fsig(float a) {
    return __fdividef(1.0f, 1.0f + __expf(-a));
}
__device__ __forceinline__ float ftanh(float a) {
    float e = __expf(2.0f * a);
    return 1.0f - __fdividef(2.0f, e + 1.0f);
}
__device__ __forceinline__ void split2(float a, float b, u32& hi2, u32& lo2) {
    __nv_bfloat16 ah = __float2bfloat16(a), bh = __float2bfloat16(b);
    __nv_bfloat16 al = __float2bfloat16(a - __bfloat162float(ah));
    __nv_bfloat16 bl = __float2bfloat16(b - __bfloat162float(bh));
    hi2 = ((u32)__bfloat16_as_ushort(bh) << 16) | __bfloat16_as_ushort(ah);
    lo2 = ((u32)__bfloat16_as_ushort(bl) << 16) | __bfloat16_as_ushort(al);
}
__device__ __forceinline__ void MMA(float acc[4], u32 a0, u32 a1, u32 a2, u32 a3,
                                    u32 b0, u32 b1) {
    asm volatile(
        "mma.sync.aligned.m16n8k16.row.col.f32.bf16.bf16.f32 "
        "{%0,%1,%2,%3}, {%4,%5,%6,%7}, {%8,%9}, {%0,%1,%2,%3};"
        : "+f"(acc[0]), "+f"(acc[1]), "+f"(acc[2]), "+f"(acc[3])
        : "r"(a0), "r"(a1), "r"(a2), "r"(a3), "r"(b0), "r"(b1));
}

// ============================ kernel 1: gi via mma.sync ============================
#define AS 72
#define WS 72

__global__ __launch_bounds__(256)
void gi_mma_kernel(const float* __restrict__ x, const float* __restrict__ eWih,
                   const float* __restrict__ eBih, const float* __restrict__ eBhh)
{
    __shared__ __nv_bfloat16 sA[128 * AS];
    __shared__ __nv_bfloat16 sW[192 * WS];
    __shared__ float sBias[192];

    const int tid  = threadIdx.x;
    const int wid  = tid >> 5;
    const int lane = tid & 31;
    const int t  = blockIdx.x >> 3;          // 0..167
    const int bq = blockIdx.x & 7;           // 8 chunks of 512 rows

    for (int i = tid; i < 192 * 32; i += 256) {
        const int o = i >> 5, c = i & 31;
        const float v = eWih[i];
        const __nv_bfloat16 hi = __float2bfloat16(v);
        sW[o * WS + c]      = hi;
        sW[o * WS + 32 + c] = __float2bfloat16(v - __bfloat162float(hi));
    }
    for (int o = tid; o < 192; o += 256)
        sBias[o] = eBih[o] + ((o < 128) ? eBhh[o] : 0.0f);

    const int g  = lane >> 2;
    const int tg = lane & 3;
    const int m0 = wid * 16;
    const int ACB[6] = {0, 16, 32, 48, 0, 16};
    const int BCB[6] = {0, 16, 0, 16, 32, 48};

    for (int it = 0; it < 4; it++) {
        const int b0 = bq * 512 + it * 128;
        __syncthreads();
        for (int i = tid; i < 128 * 32; i += 256) {
            const int r = i >> 5, c = i & 31;
            const float v = x[((size_t)(b0 + r) * TIN + t) * C_ + c];
            const __nv_bfloat16 hi = __float2bfloat16(v);
            sA[r * AS + c]      = hi;
            sA[r * AS + 32 + c] = __float2bfloat16(v - __bfloat162float(hi));
        }
        __syncthreads();

        float acc[24][4];
#pragma unroll
        for (int nt = 0; nt < 24; nt++) { acc[nt][0]=0.f; acc[nt][1]=0.f; acc[nt][2]=0.f; acc[nt][3]=0.f; }
#pragma unroll
        for (int ks = 0; ks < 6; ks++) {
            const int ac = ACB[ks], bc = BCB[ks];
            const u32 a0 = *reinterpret_cast<const u32*>(&sA[(m0 + g)     * AS + ac + 2 * tg]);
            const u32 a1 = *reinterpret_cast<const u32*>(&sA[(m0 + g + 8) * AS + ac + 2 * tg]);
            const u32 a2 = *reinterpret_cast<const u32*>(&sA[(m0 + g)     * AS + ac + 2 * tg + 8]);
            const u32 a3 = *reinterpret_cast<const u32*>(&sA[(m0 + g + 8) * AS + ac + 2 * tg + 8]);
#pragma unroll
            for (int nt = 0; nt < 24; nt++) {
                const int n = nt * 8 + g;
                const u32 b0f = *reinterpret_cast<const u32*>(&sW[n * WS + bc + 2 * tg]);
                const u32 b1f = *reinterpret_cast<const u32*>(&sW[n * WS + bc + 2 * tg + 8]);
                MMA(acc[nt], a0, a1, a2, a3, b0f, b1f);
            }
        }
        float* d0 = g_gi + ((size_t)t * B_ + b0 + m0 + g) * G3;
        float* d1 = d0 + 8 * G3;
#pragma unroll
        for (int nt = 0; nt < 24; nt++) {
            const int col = nt * 8 + 2 * tg;
            const float bi0 = sBias[col], bi1 = sBias[col + 1];
            *reinterpret_cast<float2*>(d0 + col) = make_float2(acc[nt][0] + bi0, acc[nt][1] + bi1);
            *reinterpret_cast<float2*>(d1 + col) = make_float2(acc[nt][2] + bi0, acc[nt][3] + bi1);
        }
    }
}

// ============================ kernel 2: tensor-core recurrence ============================
#define HS  136      // sH row stride (bf16): 64 hi + 64 lo + 8 pad (272B = 68 words, phase 4)
#define PS  72       // sP row stride: 32 ph + 32 pl + 8 pad
#define WDS 72       // dec Wih: 32 hi + 32 lo + 8 pad
#define PWS 136      // proj W: 64 hi + 64 lo + 8 pad

#define OFF_H   0
#define OFF_P   (2 * 32 * HS * 2)                // 17408
#define OFF_WD  (OFF_P + 2 * 32 * PS * 2)        // 26624
#define OFF_PW  (OFF_WD + 192 * WDS * 2)         // 54272
#define SM_REC  (OFF_PW + 32 * PWS * 2)          // 62976 bytes

__device__ __forceinline__ int permrow(int ln, int wq) {
    return (ln >> 4) * 64 + 16 * wq + (ln & 15);
}
__device__ __forceinline__ void load_wfrags(const float* __restrict__ W, int wq, int g, int tg,
                                            u32 bh[6][4][2], u32 bl[6][4][2]) {
#pragma unroll
    for (int nt = 0; nt < 6; nt++) {
        const float* row = W + permrow(nt * 8 + g, wq) * 64;
#pragma unroll
        for (int ks = 0; ks < 4; ks++) {
            const int k0 = ks * 16 + 2 * tg;
            split2(row[k0],     row[k0 + 1], bh[nt][ks][0], bl[nt][ks][0]);
            split2(row[k0 + 8], row[k0 + 9], bh[nt][ks][1], bl[nt][ks][1]);
        }
    }
}
#define LD_AFRAGS(dsth, dstl, base, S, r0_, r1_, tg_)                                   \
    _Pragma("unroll")                                                                    \
    for (int ks = 0; ks < 4; ks++) {                                                     \
        const int c0 = ks * 16 + 2 * (tg_);                                              \
        dsth[ks][0] = *reinterpret_cast<const u32*>(&(base)[(r0_) * (S) + c0]);          \
        dsth[ks][1] = *reinterpret_cast<const u32*>(&(base)[(r1_) * (S) + c0]);          \
        dsth[ks][2] = *reinterpret_cast<const u32*>(&(base)[(r0_) * (S) + c0 + 8]);      \
        dsth[ks][3] = *reinterpret_cast<const u32*>(&(base)[(r1_) * (S) + c0 + 8]);      \
        dstl[ks][0] = *reinterpret_cast<const u32*>(&(base)[(r0_) * (S) + 64 + c0]);     \
        dstl[ks][1] = *reinterpret_cast<const u32*>(&(base)[(r1_) * (S) + 64 + c0]);     \
        dstl[ks][2] = *reinterpret_cast<const u32*>(&(base)[(r0_) * (S) + 64 + c0 + 8]); \
        dstl[ks][3] = *reinterpret_cast<const u32*>(&(base)[(r1_) * (S) + 64 + c0 + 8]); \
    }

__global__ __launch_bounds__(256)
void gru_rec_mma(const float* __restrict__ x,
                 const float* __restrict__ eWhh, const float* __restrict__ eBhh,
                 const float* __restrict__ dWih, const float* __restrict__ dWhh,
                 const float* __restrict__ dBih, const float* __restrict__ dBhh,
                 const float* __restrict__ pW,   const float* __restrict__ pB,
                 float* __restrict__ out)
{
    extern __shared__ __align__(16) char smem[];
    __nv_bfloat16* sH  = reinterpret_cast<__nv_bfloat16*>(smem + OFF_H);   // [2][32][HS]
    __nv_bfloat16* sP  = reinterpret_cast<__nv_bfloat16*>(smem + OFF_P);   // [2][32][PS]
    __nv_bfloat16* sWd = reinterpret_cast<__nv_bfloat16*>(smem + OFF_WD);  // [192][WDS]
    __nv_bfloat16* sPm = reinterpret_cast<__nv_bfloat16*>(smem + OFF_PW);  // [32][PWS]

    const int tid  = threadIdx.x;
    const int wid  = tid >> 5;
    const int lane = tid & 31;
    const int g  = lane >> 2;
    const int tg = lane & 3;
    const int mh = wid >> 2;      // m-half: rows mh*16..+15
    const int wq = wid & 3;       // n-quad: units 16wq..16wq+15
    const int m0 = mh * 16;
    const int r0 = m0 + g, r1 = m0 + g + 8;
    const int rowbase = blockIdx.x * 32;

    // ---- stage decoder weights (pre-split) + zero h buffers ----
    for (int i = tid; i < 192 * 32; i += 256) {
        const int o = i >> 5, c = i & 31;
        const float v = dWih[i];
        const __nv_bfloat16 hi = __float2bfloat16(v);
        sWd[o * WDS + c]      = hi;
        sWd[o * WDS + 32 + c] = __float2bfloat16(v - __bfloat162float(hi));
    }
    for (int i = tid; i < 32 * 64; i += 256) {
        const int o = i >> 6, c = i & 63;
        const float v = pW[i];
        const __nv_bfloat16 hi = __float2bfloat16(v);
        sPm[o * PWS + c]      = hi;
        sPm[o * PWS + 64 + c] = __float2bfloat16(v - __bfloat162float(hi));
    }
    for (int i = tid; i < 2 * 32 * HS; i += 256)
        reinterpret_cast<unsigned short*>(sH)[i] = 0;

    // ---- encoder Whh fragments (hi/lo) into registers ----
    u32 bh[6][4][2], bl[6][4][2];
    load_wfrags(eWhh, wq, g, tg, bh, bl);
    float bhn[4];
#pragma unroll
    for (int sp = 0; sp < 4; sp++)
        bhn[sp] = eBhh[128 + 16 * wq + (sp >> 1) * 8 + 2 * tg + (sp & 1)];

    __syncthreads();

    float h[8];
#pragma unroll
    for (int e = 0; e < 8; e++) h[e] = 0.0f;
    int hp = 0;

    // ======================= encoder: 168 steps =======================
    for (int t = 0; t < TIN; t++) {
        // gi loads (issued early; consumed after MMA)
        const float* gb = g_gi + ((size_t)t * B_ + rowbase + r0) * G3 + 16 * wq + 2 * tg;
        float gv[24];
#pragma unroll
        for (int rh = 0; rh < 2; rh++) {
            const float* gp = gb + rh * 8 * G3;
#pragma unroll
            for (int sp = 0; sp < 4; sp++) {
                const int off = (sp >> 1) * 8 + (sp & 1), e = rh * 4 + sp;
                gv[e]      = __ldg(gp + off);
                gv[8 + e]  = __ldg(gp + 64 + off);
                gv[16 + e] = __ldg(gp + 128 + off);
            }
        }
        const __nv_bfloat16* hb = sH + hp * 32 * HS;
        u32 ah4[4][4], al4[4][4];
        LD_AFRAGS(ah4, al4, hb, HS, r0, r1, tg);

        float acc[6][4];
#pragma unroll
        for (int nt = 0; nt < 6; nt++) {
            acc[nt][0]=0.f; acc[nt][1]=0.f; acc[nt][2]=0.f; acc[nt][3]=0.f;
#pragma unroll
            for (int ks = 0; ks < 4; ks++)
                MMA(acc[nt], ah4[ks][0], ah4[ks][1], ah4[ks][2], ah4[ks][3], bh[nt][ks][0], bh[nt][ks][1]);
#pragma unroll
            for (int ks = 0; ks < 4; ks++)
                MMA(acc[nt], al4[ks][0], al4[ks][1], al4[ks][2], al4[ks][3], bh[nt][ks][0], bh[nt][ks][1]);
#pragma unroll
            for (int ks = 0; ks < 4; ks++)
                MMA(acc[nt], ah4[ks][0], ah4[ks][1], ah4[ks][2], ah4[ks][3], bl[nt][ks][0], bl[nt][ks][1]);
        }

        __nv_bfloat16* hw = sH + (hp ^ 1) * 32 * HS;
#pragma unroll
        for (int rh = 0; rh < 2; rh++) {
#pragma unroll
            for (int s = 0; s < 2; s++) {
                const int e = rh * 4 + s * 2;
                const float rg0 = fsig(acc[s][2*rh]   + gv[e]);
                const float rg1 = fsig(acc[s][2*rh+1] + gv[e+1]);
                const float z0  = fsig(acc[2+s][2*rh]   + gv[8+e]);
                const float z1  = fsig(acc[2+s][2*rh+1] + gv[8+e+1]);
                const float n0  = ftanh(fmaf(rg0, acc[4+s][2*rh]   + bhn[s*2],   gv[16+e]));
                const float n1  = ftanh(fmaf(rg1, acc[4+s][2*rh+1] + bhn[s*2+1], gv[16+e+1]));
                h[e]   = (1.0f - z0) * n0 + z0 * h[e];
                h[e+1] = (1.0f - z1) * n1 + z1 * h[e+1];
                u32 vh, vl; split2(h[e], h[e+1], vh, vl);
                const int row = rh ? r1 : r0;
                const int col = 16 * wq + s * 8 + 2 * tg;
                *reinterpret_cast<u32*>(&hw[row * HS + col])      = vh;
                *reinterpret_cast<u32*>(&hw[row * HS + 64 + col]) = vl;
            }
        }
        asm volatile("bar.sync %0, %1;" :: "r"(1 + mh), "r"(128) : "memory");
        hp ^= 1;
    }

    // ======================= decoder: 24 steps =======================
    load_wfrags(dWhh, wq, g, tg, bh, bl);   // overwrite with decoder Whh
    float dbr[4], dbz[4], dni[4], dnh[4];
#pragma unroll
    for (int sp = 0; sp < 4; sp++) {
        const int u = 16 * wq + (sp >> 1) * 8 + 2 * tg + (sp & 1);
        dbr[sp] = dBih[u] + dBhh[u];
        dbz[sp] = dBih[64 + u] + dBhh[64 + u];
        dni[sp] = dBih[128 + u];
        dnh[sp] = dBhh[128 + u];
    }
    const float pb0 = pB[8 * wq + 2 * tg], pb1 = pB[8 * wq + 2 * tg + 1];

    // prev_0 = x[:, TIN-1, :] (split)
    for (int i = tid; i < 32 * 32; i += 256) {
        const int rw = i >> 5, c = i & 31;
        const float v = x[((size_t)(rowbase + rw) * TIN + (TIN - 1)) * C_ + c];
        const __nv_bfloat16 hi = __float2bfloat16(v);
        sP[rw * PS + c]      = hi;
        sP[rw * PS + 32 + c] = __float2bfloat16(v - __bfloat162float(hi));
    }
    __syncthreads();

    int pp = 0;
    for (int t = 0; t < TOUT; t++) {
        const __nv_bfloat16* hb = sH + hp * 32 * HS;
        const __nv_bfloat16* pbuf = sP + pp * 32 * PS;
        u32 ah4[4][4], al4[4][4];
        LD_AFRAGS(ah4, al4, hb, HS, r0, r1, tg);
        u32 aph[2][4], apl[2][4];
#pragma unroll
        for (int ks = 0; ks < 2; ks++) {
            const int c0 = ks * 16 + 2 * tg;
            aph[ks][0] = *reinterpret_cast<const u32*>(&pbuf[r0 * PS + c0]);
            aph[ks][1] = *reinterpret_cast<const u32*>(&pbuf[r1 * PS + c0]);
            aph[ks][2] = *reinterpret_cast<const u32*>(&pbuf[r0 * PS + c0 + 8]);
            aph[ks][3] = *reinterpret_cast<const u32*>(&pbuf[r1 * PS + c0 + 8]);
            apl[ks][0] = *reinterpret_cast<const u32*>(&pbuf[r0 * PS + 32 + c0]);
            apl[ks][1] = *reinterpret_cast<const u32*>(&pbuf[r1 * PS + 32 + c0]);
            apl[ks][2] = *reinterpret_cast<const u32*>(&pbuf[r0 * PS + 32 + c0 + 8]);
            apl[ks][3] = *reinterpret_cast<const u32*>(&pbuf[r1 * PS + 32 + c0 + 8]);
        }

        float accW[6][4], accP[2][4];
#pragma unroll
        for (int q = 0; q < 2; q++) { accP[q][0]=0.f; accP[q][1]=0.f; accP[q][2]=0.f; accP[q][3]=0.f; }
#pragma unroll
        for (int nt = 0; nt < 6; nt++) {
            float* A = accW[nt];
            A[0]=0.f; A[1]=0.f; A[2]=0.f; A[3]=0.f;
#pragma unroll
            for (int ks = 0; ks < 4; ks++)
                MMA(A, ah4[ks][0], ah4[ks][1], ah4[ks][2], ah4[ks][3], bh[nt][ks][0], bh[nt][ks][1]);
#pragma unroll
            for (int ks = 0; ks < 4; ks++)
                MMA(A, al4[ks][0], al4[ks][1], al4[ks][2], al4[ks][3], bh[nt][ks][0], bh[nt][ks][1]);
#pragma unroll
            for (int ks = 0; ks < 4; ks++)
                MMA(A, ah4[ks][0], ah4[ks][1], ah4[ks][2], ah4[ks][3], bl[nt][ks][0], bl[nt][ks][1]);
            // Wih @ prev  (n-gate products kept separate in accP)
            float* T = (nt < 4) ? A : accP[nt - 4];
            const int prow = permrow(nt * 8 + g, wq);
#pragma unroll
            for (int ks = 0; ks < 2; ks++) {
                const int c0 = ks * 16 + 2 * tg;
                const u32 wh0 = *reinterpret_cast<const u32*>(&sWd[prow * WDS + c0]);
                const u32 wh1 = *reinterpret_cast<const u32*>(&sWd[prow * WDS + c0 + 8]);
                const u32 wl0 = *reinterpret_cast<const u32*>(&sWd[prow * WDS + 32 + c0]);
                const u32 wl1 = *reinterpret_cast<const u32*>(&sWd[prow * WDS + 32 + c0 + 8]);
                MMA(T, aph[ks][0], aph[ks][1], aph[ks][2], aph[ks][3], wh0, wh1);
                MMA(T, apl[ks][0], apl[ks][1], apl[ks][2], apl[ks][3], wh0, wh1);
                MMA(T, aph[ks][0], aph[ks][1], aph[ks][2], aph[ks][3], wl0, wl1);
            }
        }

        __nv_bfloat16* hw = sH + (hp ^ 1) * 32 * HS;
#pragma unroll
        for (int rh = 0; rh < 2; rh++) {
#pragma unroll
            for (int s = 0; s < 2; s++) {
                const int e = rh * 4 + s * 2;
                const float rg0 = fsig(accW[s][2*rh]   + dbr[s*2]);
                const float rg1 = fsig(accW[s][2*rh+1] + dbr[s*2+1]);
                const float z0  = fsig(accW[2+s][2*rh]   + dbz[s*2]);
                const float z1  = fsig(accW[2+s][2*rh+1] + dbz[s*2+1]);
                const float n0  = ftanh(accP[s][2*rh]   + dni[s*2]   + rg0 * (accW[4+s][2*rh]   + dnh[s*2]));
                const float n1  = ftanh(accP[s][2*rh+1] + dni[s*2+1] + rg1 * (accW[4+s][2*rh+1] + dnh[s*2+1]));
                h[e]   = (1.0f - z0) * n0 + z0 * h[e];
                h[e+1] = (1.0f - z1) * n1 + z1 * h[e+1];
                u32 vh, vl; split2(h[e], h[e+1], vh, vl);
                const int row = rh ? r1 : r0;
                const int col = 16 * wq + s * 8 + 2 * tg;
                *reinterpret_cast<u32*>(&hw[row * HS + col])      = vh;
                *reinterpret_cast<u32*>(&hw[row * HS + 64 + col]) = vl;
            }
        }
        asm volatile("bar.sync %0, %1;" :: "r"(1 + mh), "r"(128) : "memory");

        // ---- projection from NEW h splits ----
        {
            const __nv_bfloat16* hn = sH + (hp ^ 1) * 32 * HS;
            u32 nh4[4][4], nl4[4][4];
            LD_AFRAGS(nh4, nl4, hn, HS, r0, r1, tg);
            const int prow = 8 * wq + g;
            float pacc[4] = {0.f, 0.f, 0.f, 0.f};
#pragma unroll
            for (int ks = 0; ks < 4; ks++) {
                const int c0 = ks * 16 + 2 * tg;
                const u32 wh0 = *reinterpret_cast<const u32*>(&sPm[prow * PWS + c0]);
                const u32 wh1 = *reinterpret_cast<const u32*>(&sPm[prow * PWS + c0 + 8]);
                const u32 wl0 = *reinterpret_cast<const u32*>(&sPm[prow * PWS + 64 + c0]);
                const u32 wl1 = *reinterpret_cast<const u32*>(&sPm[prow * PWS + 64 + c0 + 8]);
                MMA(pacc, nh4[ks][0], nh4[ks][1], nh4[ks][2], nh4[ks][3], wh0, wh1);
                MMA(pacc, nl4[ks][0], nl4[ks][1], nl4[ks][2], nl4[ks][3], wh0, wh1);
                MMA(pacc, nh4[ks][0], nh4[ks][1], nh4[ks][2], nh4[ks][3], wl0, wl1);
            }
            const float p00 = pacc[0] + pb0, p01 = pacc[1] + pb1;
            const float p10 = pacc[2] + pb0, p11 = pacc[3] + pb1;
            const int col = 8 * wq + 2 * tg;
            *reinterpret_cast<float2*>(&out[((size_t)(rowbase + r0) * TOUT + t) * C_ + col]) = make_float2(p00, p01);
            *reinterpret_cast<float2*>(&out[((size_t)(rowbase + r1) * TOUT + t) * C_ + col]) = make_float2(p10, p11);
            __nv_bfloat16* pn = sP + (pp ^ 1) * 32 * PS;
            u32 vh, vl;
            split2(p00, p01, vh, vl);
            *reinterpret_cast<u32*>(&pn[r0 * PS + col])      = vh;
            *reinterpret_cast<u32*>(&pn[r0 * PS + 32 + col]) = vl;
            split2(p10, p11, vh, vl);
            *reinterpret_cast<u32*>(&pn[r1 * PS + col])      = vh;
            *reinterpret_cast<u32*>(&pn[r1 * PS + 32 + col]) = vl;
        }
        asm volatile("bar.sync %0, %1;" :: "r"(1 + mh), "r"(128) : "memory");
        hp ^= 1; pp ^= 1;
    }
}

// ============================ launch ============================
extern "C" void kernel_launch(void* const* d_in, const int* in_sizes, int n_in,
                              void* d_out, int out_size)
{
    (void)in_sizes; (void)n_in; (void)out_size;
    const float* x    = (const float*)d_in[0];
    const float* eWih = (const float*)d_in[1];
    const float* eWhh = (const float*)d_in[2];
    const float* eBih = (const float*)d_in[3];
    const float* eBhh = (const float*)d_in[4];
    const float* dWih = (const float*)d_in[5];
    const float* dWhh = (const float*)d_in[6];
    const float* dBih = (const float*)d_in[7];
    const float* dBhh = (const float*)d_in[8];
    const float* pW   = (const float*)d_in[9];
    const float* pB   = (const float*)d_in[10];
    float* out = (float*)d_out;

    gi_mma_kernel<<<TIN * 8, 256>>>(x, eWih, eBih, eBhh);

    cudaFuncSetAttribute(gru_rec_mma,
                         cudaFuncAttributeMaxDynamicSharedMemorySize, SM_REC);
    gru_rec_mma<<<B_ / 32, 256, SM_REC>>>(
        x, eWhh, eBhh, dWih, dWhh, dBih, dBhh, pW, pB, out);
}

// round 9
// speedup vs baseline: 3.7253x; 1.5318x over previous
#include <cuda_runtime.h>
#include <cuda_bf16.h>
#include <cstdint>

// GRU seq2seq forecaster — fully fused tensor-core recurrence.
//  K0: xsplit — pre-split x into bf16 hi/lo records [t][b]{32 hi, 32 lo}.
//  K1: fused recurrence: per step, h@Whh (regs B-frags) + x@Wih (smem frag-major
//      B-frags, cp.async-prefetched x A-frags). Gates straight from accumulators.
//      Decoder identical plus projection. No gi scratch.

#define B_    4096
#define TIN   168
#define C_    32
#define H_    64
#define TOUT  24

typedef uint32_t u32;

__device__ __nv_bfloat16 g_xs[(size_t)TIN * B_ * 64];   // 88 MB pre-split x

__device__ __forceinline__ float fsig(float a) {
    return __fdividef(1.0f, 1.0f + __expf(-a));
}
__device__ __forceinline__ float ftanh(float a) {
    float e = __expf(2.0f * a);
    return 1.0f - __fdividef(2.0f, e + 1.0f);
}
__device__ __forceinline__ void split2(float a, float b, u32& hi2, u32& lo2) {
    __nv_bfloat16 ah = __float2bfloat16(a), bh = __float2bfloat16(b);
    __nv_bfloat16 al = __float2bfloat16(a - __bfloat162float(ah));
    __nv_bfloat16 bl = __float2bfloat16(b - __bfloat162float(bh));
    hi2 = ((u32)__bfloat16_as_ushort(bh) << 16) | __bfloat16_as_ushort(ah);
    lo2 = ((u32)__bfloat16_as_ushort(bl) << 16) | __bfloat16_as_ushort(al);
}
__device__ __forceinline__ void MMA(float acc[4], u32 a0, u32 a1, u32 a2, u32 a3,
                                    u32 b0, u32 b1) {
    asm volatile(
        "mma.sync.aligned.m16n8k16.row.col.f32.bf16.bf16.f32 "
        "{%0,%1,%2,%3}, {%4,%5,%6,%7}, {%8,%9}, {%0,%1,%2,%3};"
        : "+f"(acc[0]), "+f"(acc[1]), "+f"(acc[2]), "+f"(acc[3])
        : "r"(a0), "r"(a1), "r"(a2), "r"(a3), "r"(b0), "r"(b1));
}
__device__ __forceinline__ u32 smem_u32(const void* p) {
    u32 a;
    asm("{ .reg .u64 t; cvta.to.shared.u64 t, %1; cvt.u32.u64 %0, t; }" : "=r"(a) : "l"(p));
    return a;
}
__device__ __forceinline__ void cp16(u32 daddr, const void* gsrc) {
    asm volatile("cp.async.cg.shared.global [%0], [%1], 16;"
                 :: "r"(daddr), "l"(gsrc) : "memory");
}

// ============================ kernel 0: x pre-split ============================
__global__ __launch_bounds__(256)
void xsplit_kernel(const float* __restrict__ x)
{
    const int p    = blockIdx.x * 128 + (threadIdx.x >> 1);   // (t,b) index: t=p>>12
    const int half = threadIdx.x & 1;
    const int t = p >> 12, b = p & (B_ - 1);
    const float4* src = reinterpret_cast<const float4*>(x + ((size_t)b * TIN + t) * C_ + 16 * half);
    u32 hw[8], lw[8];
#pragma unroll
    for (int q = 0; q < 4; q++) {
        float4 v = src[q];
        split2(v.x, v.y, hw[2*q],   lw[2*q]);
        split2(v.z, v.w, hw[2*q+1], lw[2*q+1]);
    }
    char* dst = reinterpret_cast<char*>(g_xs) + (size_t)p * 128;
    *reinterpret_cast<uint4*>(dst + 32*half)           = make_uint4(hw[0],hw[1],hw[2],hw[3]);
    *reinterpret_cast<uint4*>(dst + 32*half + 16)      = make_uint4(hw[4],hw[5],hw[6],hw[7]);
    *reinterpret_cast<uint4*>(dst + 64 + 32*half)      = make_uint4(lw[0],lw[1],lw[2],lw[3]);
    *reinterpret_cast<uint4*>(dst + 64 + 32*half + 16) = make_uint4(lw[4],lw[5],lw[6],lw[7]);
}

// ============================ kernel 1: fused recurrence ============================
#define HS  136      // sH row stride (bf16)
#define PS  72       // sP row stride (bf16)
#define XSTR 36      // x tile row stride (u32) = 144B (128B data + 16B pad)

#define OFF_H   0                        // [2][32][HS] bf16        = 17408
#define OFF_P   17408                    // [2][32][PS] bf16        =  9216
#define OFF_X   26624                    // [2][32][XSTR u32]       =  9216
#define OFF_WF  35840                    // [4][6][2][32] uint4     = 24576
#define OFF_PF  60416                    // [4][4][32] uint4        =  8192
#define SM_TOTAL 68608

__device__ __forceinline__ int permrow(int ln, int wq) {
    return (ln >> 4) * 64 + 16 * wq + (ln & 15);
}
__device__ __forceinline__ void load_wfrags(const float* __restrict__ W, int wq, int g, int tg,
                                            u32 bh[6][4][2], u32 bl[6][4][2]) {
#pragma unroll
    for (int nt = 0; nt < 6; nt++) {
        const float* row = W + permrow(nt * 8 + g, wq) * 64;
#pragma unroll
        for (int ks = 0; ks < 4; ks++) {
            const int k0 = ks * 16 + 2 * tg;
            split2(row[k0],     row[k0 + 1], bh[nt][ks][0], bl[nt][ks][0]);
            split2(row[k0 + 8], row[k0 + 9], bh[nt][ks][1], bl[nt][ks][1]);
        }
    }
}
#define LD_AFRAGS(dsth, dstl, base, S, r0_, r1_, tg_)                                   \
    _Pragma("unroll")                                                                    \
    for (int ks = 0; ks < 4; ks++) {                                                     \
        const int c0 = ks * 16 + 2 * (tg_);                                              \
        dsth[ks][0] = *reinterpret_cast<const u32*>(&(base)[(r0_) * (S) + c0]);          \
        dsth[ks][1] = *reinterpret_cast<const u32*>(&(base)[(r1_) * (S) + c0]);          \
        dsth[ks][2] = *reinterpret_cast<const u32*>(&(base)[(r0_) * (S) + c0 + 8]);      \
        dsth[ks][3] = *reinterpret_cast<const u32*>(&(base)[(r1_) * (S) + c0 + 8]);      \
        dstl[ks][0] = *reinterpret_cast<const u32*>(&(base)[(r0_) * (S) + 64 + c0]);     \
        dstl[ks][1] = *reinterpret_cast<const u32*>(&(base)[(r1_) * (S) + 64 + c0]);     \
        dstl[ks][2] = *reinterpret_cast<const u32*>(&(base)[(r0_) * (S) + 64 + c0 + 8]); \
        dstl[ks][3] = *reinterpret_cast<const u32*>(&(base)[(r1_) * (S) + 64 + c0 + 8]); \
    }

__global__ __launch_bounds__(256)
void gru_fused(const float* __restrict__ x,
               const float* __restrict__ eWih, const float* __restrict__ eWhh,
               const float* __restrict__ eBih, const float* __restrict__ eBhh,
               const float* __restrict__ dWih, const float* __restrict__ dWhh,
               const float* __restrict__ dBih, const float* __restrict__ dBhh,
               const float* __restrict__ pW,   const float* __restrict__ pB,
               float* __restrict__ out)
{
    extern __shared__ __align__(16) char smem[];
    __nv_bfloat16* sH = reinterpret_cast<__nv_bfloat16*>(smem + OFF_H);
    __nv_bfloat16* sP = reinterpret_cast<__nv_bfloat16*>(smem + OFF_P);
    const u32* sX     = reinterpret_cast<const u32*>(smem + OFF_X);
    uint4* sWf        = reinterpret_cast<uint4*>(smem + OFF_WF);
    uint4* sPf        = reinterpret_cast<uint4*>(smem + OFF_PF);
    const u32 smb = smem_u32(smem);

    const int tid  = threadIdx.x;
    const int wid  = tid >> 5;
    const int lane = tid & 31;
    const int g  = lane >> 2;
    const int tg = lane & 3;
    const int mh = wid >> 2;
    const int wq = wid & 3;
    const int m0 = mh * 16;
    const int r0 = m0 + g, r1 = m0 + g + 8;
    const int rowbase = blockIdx.x * 32;
    const int ldrow = tid >> 3, ldchunk = tid & 7;   // cp.async roles (row 0..31, 16B chunk)

    // ---- init: zero h buffers, stage encoder Wih frags ----
    for (int i = tid; i < 2 * 32 * HS; i += 256)
        reinterpret_cast<unsigned short*>(sH)[i] = 0;
    if (mh == 0) {
#pragma unroll
        for (int nt = 0; nt < 6; nt++)
#pragma unroll
            for (int ks = 0; ks < 2; ks++) {
                const float* wr = eWih + permrow(nt * 8 + g, wq) * 32 + ks * 16 + 2 * tg;
                u32 h0, l0, h1, l1;
                split2(wr[0], wr[1], h0, l0);
                split2(wr[8], wr[9], h1, l1);
                sWf[((wq * 6 + nt) * 2 + ks) * 32 + lane] = make_uint4(h0, h1, l0, l1);
            }
    }
    u32 bh[6][4][2], bl[6][4][2];
    load_wfrags(eWhh, wq, g, tg, bh, bl);
    float ebr[4], ebz[4], eni[4], enh[4];
#pragma unroll
    for (int sp = 0; sp < 4; sp++) {
        const int u = 16 * wq + (sp >> 1) * 8 + 2 * tg + (sp & 1);
        ebr[sp] = eBih[u] + eBhh[u];
        ebz[sp] = eBih[64 + u] + eBhh[64 + u];
        eni[sp] = eBih[128 + u];
        enh[sp] = eBhh[128 + u];
    }
    __syncthreads();

    // prologue: prefetch x tile t=0
    {
        const char* src = reinterpret_cast<const char*>(g_xs)
                        + ((size_t)(rowbase + ldrow)) * 128 + ldchunk * 16;
        cp16(smb + OFF_X + ldrow * 144 + ldchunk * 16, src);
        asm volatile("cp.async.commit_group;" ::: "memory");
    }

    float h[8];
#pragma unroll
    for (int e = 0; e < 8; e++) h[e] = 0.0f;
    int hp = 0;

    // ======================= encoder: 168 steps =======================
    for (int t = 0; t < TIN; t++) {
        asm volatile("cp.async.wait_group 0;" ::: "memory");
        asm volatile("bar.sync %0, %1;" :: "r"(1 + mh), "r"(128) : "memory");
        if (t + 1 < TIN) {   // prefetch next tile (overlaps this step's compute)
            const char* src = reinterpret_cast<const char*>(g_xs)
                            + ((size_t)(t + 1) * B_ + rowbase + ldrow) * 128 + ldchunk * 16;
            cp16(smb + OFF_X + ((t + 1) & 1) * 4608 + ldrow * 144 + ldchunk * 16, src);
            asm volatile("cp.async.commit_group;" ::: "memory");
        }

        const __nv_bfloat16* hb = sH + hp * 32 * HS;
        u32 ah4[4][4], al4[4][4];
        LD_AFRAGS(ah4, al4, hb, HS, r0, r1, tg);
        const u32* xb = sX + (t & 1) * 1152;
        u32 xh[2][4], xl[2][4];
#pragma unroll
        for (int ks = 0; ks < 2; ks++) {
            const int i0 = r0 * XSTR + 8 * ks + tg, i1 = r1 * XSTR + 8 * ks + tg;
            xh[ks][0] = xb[i0];      xh[ks][1] = xb[i1];
            xh[ks][2] = xb[i0 + 4];  xh[ks][3] = xb[i1 + 4];
            xl[ks][0] = xb[i0 + 16]; xl[ks][1] = xb[i1 + 16];
            xl[ks][2] = xb[i0 + 20]; xl[ks][3] = xb[i1 + 20];
        }

        float accW[6][4], accP[2][4];
#pragma unroll
        for (int q = 0; q < 2; q++) { accP[q][0]=0.f; accP[q][1]=0.f; accP[q][2]=0.f; accP[q][3]=0.f; }
#pragma unroll
        for (int nt = 0; nt < 6; nt++) {
            float* A = accW[nt];
            A[0]=0.f; A[1]=0.f; A[2]=0.f; A[3]=0.f;
#pragma unroll
            for (int ks = 0; ks < 4; ks++)
                MMA(A, ah4[ks][0], ah4[ks][1], ah4[ks][2], ah4[ks][3], bh[nt][ks][0], bh[nt][ks][1]);
#pragma unroll
            for (int ks = 0; ks < 4; ks++)
                MMA(A, al4[ks][0], al4[ks][1], al4[ks][2], al4[ks][3], bh[nt][ks][0], bh[nt][ks][1]);
#pragma unroll
            for (int ks = 0; ks < 4; ks++)
                MMA(A, ah4[ks][0], ah4[ks][1], ah4[ks][2], ah4[ks][3], bl[nt][ks][0], bl[nt][ks][1]);
            float* T = (nt < 4) ? A : accP[nt - 4];
#pragma unroll
            for (int ks = 0; ks < 2; ks++) {
                const uint4 w = sWf[((wq * 6 + nt) * 2 + ks) * 32 + lane];
                MMA(T, xh[ks][0], xh[ks][1], xh[ks][2], xh[ks][3], w.x, w.y);
                MMA(T, xl[ks][0], xl[ks][1], xl[ks][2], xl[ks][3], w.x, w.y);
                MMA(T, xh[ks][0], xh[ks][1], xh[ks][2], xh[ks][3], w.z, w.w);
            }
        }

        __nv_bfloat16* hw = sH + (hp ^ 1) * 32 * HS;
#pragma unroll
        for (int rh = 0; rh < 2; rh++) {
#pragma unroll
            for (int s = 0; s < 2; s++) {
                const int e = rh * 4 + s * 2;
                const float rg0 = fsig(accW[s][2*rh]   + ebr[s*2]);
                const float rg1 = fsig(accW[s][2*rh+1] + ebr[s*2+1]);
                const float z0  = fsig(accW[2+s][2*rh]   + ebz[s*2]);
                const float z1  = fsig(accW[2+s][2*rh+1] + ebz[s*2+1]);
                const float n0  = ftanh(accP[s][2*rh]   + eni[s*2]   + rg0 * (accW[4+s][2*rh]   + enh[s*2]));
                const float n1  = ftanh(accP[s][2*rh+1] + eni[s*2+1] + rg1 * (accW[4+s][2*rh+1] + enh[s*2+1]));
                h[e]   = (1.0f - z0) * n0 + z0 * h[e];
                h[e+1] = (1.0f - z1) * n1 + z1 * h[e+1];
                u32 vh, vl; split2(h[e], h[e+1], vh, vl);
                const int row = rh ? r1 : r0;
                const int col = 16 * wq + s * 8 + 2 * tg;
                *reinterpret_cast<u32*>(&hw[row * HS + col])      = vh;
                *reinterpret_cast<u32*>(&hw[row * HS + 64 + col]) = vl;
            }
        }
        hp ^= 1;
    }

    // ======================= decoder: 24 steps =======================
    __syncthreads();
    if (mh == 0) {   // restage frag-major: decoder Wih + projection W
#pragma unroll
        for (int nt = 0; nt < 6; nt++)
#pragma unroll
            for (int ks = 0; ks < 2; ks++) {
                const float* wr = dWih + permrow(nt * 8 + g, wq) * 32 + ks * 16 + 2 * tg;
                u32 h0, l0, h1, l1;
                split2(wr[0], wr[1], h0, l0);
                split2(wr[8], wr[9], h1, l1);
                sWf[((wq * 6 + nt) * 2 + ks) * 32 + lane] = make_uint4(h0, h1, l0, l1);
            }
#pragma unroll
        for (int ks = 0; ks < 4; ks++) {
            const float* wr = pW + (8 * wq + g) * 64 + ks * 16 + 2 * tg;
            u32 h0, l0, h1, l1;
            split2(wr[0], wr[1], h0, l0);
            split2(wr[8], wr[9], h1, l1);
            sPf[(wq * 4 + ks) * 32 + lane] = make_uint4(h0, h1, l0, l1);
        }
    }
    load_wfrags(dWhh, wq, g, tg, bh, bl);
    float dbr[4], dbz[4], dni[4], dnh[4];
#pragma unroll
    for (int sp = 0; sp < 4; sp++) {
        const int u = 16 * wq + (sp >> 1) * 8 + 2 * tg + (sp & 1);
        dbr[sp] = dBih[u] + dBhh[u];
        dbz[sp] = dBih[64 + u] + dBhh[64 + u];
        dni[sp] = dBih[128 + u];
        dnh[sp] = dBhh[128 + u];
    }
    const float pb0 = pB[8 * wq + 2 * tg], pb1 = pB[8 * wq + 2 * tg + 1];

    for (int i = tid; i < 32 * 32; i += 256) {   // prev_0 = x[:, TIN-1, :]
        const int rw = i >> 5, c = i & 31;
        const float v = x[((size_t)(rowbase + rw) * TIN + (TIN - 1)) * C_ + c];
        const __nv_bfloat16 hi = __float2bfloat16(v);
        sP[rw * PS + c]      = hi;
        sP[rw * PS + 32 + c] = __float2bfloat16(v - __bfloat162float(hi));
    }
    __syncthreads();

    int pp = 0;
    for (int t = 0; t < TOUT; t++) {
        const __nv_bfloat16* hb = sH + hp * 32 * HS;
        const __nv_bfloat16* pbuf = sP + pp * 32 * PS;
        u32 ah4[4][4], al4[4][4];
        LD_AFRAGS(ah4, al4, hb, HS, r0, r1, tg);
        u32 aph[2][4], apl[2][4];
#pragma unroll
        for (int ks = 0; ks < 2; ks++) {
            const int c0 = ks * 16 + 2 * tg;
            aph[ks][0] = *reinterpret_cast<const u32*>(&pbuf[r0 * PS + c0]);
            aph[ks][1] = *reinterpret_cast<const u32*>(&pbuf[r1 * PS + c0]);
            aph[ks][2] = *reinterpret_cast<const u32*>(&pbuf[r0 * PS + c0 + 8]);
            aph[ks][3] = *reinterpret_cast<const u32*>(&pbuf[r1 * PS + c0 + 8]);
            apl[ks][0] = *reinterpret_cast<const u32*>(&pbuf[r0 * PS + 32 + c0]);
            apl[ks][1] = *reinterpret_cast<const u32*>(&pbuf[r1 * PS + 32 + c0]);
            apl[ks][2] = *reinterpret_cast<const u32*>(&pbuf[r0 * PS + 32 + c0 + 8]);
            apl[ks][3] = *reinterpret_cast<const u32*>(&pbuf[r1 * PS + 32 + c0 + 8]);
        }

        float accW[6][4], accP[2][4];
#pragma unroll
        for (int q = 0; q < 2; q++) { accP[q][0]=0.f; accP[q][1]=0.f; accP[q][2]=0.f; accP[q][3]=0.f; }
#pragma unroll
        for (int nt = 0; nt < 6; nt++) {
            float* A = accW[nt];
            A[0]=0.f; A[1]=0.f; A[2]=0.f; A[3]=0.f;
#pragma unroll
            for (int ks = 0; ks < 4; ks++)
                MMA(A, ah4[ks][0], ah4[ks][1], ah4[ks][2], ah4[ks][3], bh[nt][ks][0], bh[nt][ks][1]);
#pragma unroll
            for (int ks = 0; ks < 4; ks++)
                MMA(A, al4[ks][0], al4[ks][1], al4[ks][2], al4[ks][3], bh[nt][ks][0], bh[nt][ks][1]);
#pragma unroll
            for (int ks = 0; ks < 4; ks++)
                MMA(A, ah4[ks][0], ah4[ks][1], ah4[ks][2], ah4[ks][3], bl[nt][ks][0], bl[nt][ks][1]);
            float* T = (nt < 4) ? A : accP[nt - 4];
#pragma unroll
            for (int ks = 0; ks < 2; ks++) {
                const uint4 w = sWf[((wq * 6 + nt) * 2 + ks) * 32 + lane];
                MMA(T, aph[ks][0], aph[ks][1], aph[ks][2], aph[ks][3], w.x, w.y);
                MMA(T, apl[ks][0], apl[ks][1], apl[ks][2], apl[ks][3], w.x, w.y);
                MMA(T, aph[ks][0], aph[ks][1], aph[ks][2], aph[ks][3], w.z, w.w);
            }
        }

        __nv_bfloat16* hw = sH + (hp ^ 1) * 32 * HS;
#pragma unroll
        for (int rh = 0; rh < 2; rh++) {
#pragma unroll
            for (int s = 0; s < 2; s++) {
                const int e = rh * 4 + s * 2;
                const float rg0 = fsig(accW[s][2*rh]   + dbr[s*2]);
                const float rg1 = fsig(accW[s][2*rh+1] + dbr[s*2+1]);
                const float z0  = fsig(accW[2+s][2*rh]   + dbz[s*2]);
                const float z1  = fsig(accW[2+s][2*rh+1] + dbz[s*2+1]);
                const float n0  = ftanh(accP[s][2*rh]   + dni[s*2]   + rg0 * (accW[4+s][2*rh]   + dnh[s*2]));
                const float n1  = ftanh(accP[s][2*rh+1] + dni[s*2+1] + rg1 * (accW[4+s][2*rh+1] + dnh[s*2+1]));
                h[e]   = (1.0f - z0) * n0 + z0 * h[e];
                h[e+1] = (1.0f - z1) * n1 + z1 * h[e+1];
                u32 vh, vl; split2(h[e], h[e+1], vh, vl);
                const int row = rh ? r1 : r0;
                const int col = 16 * wq + s * 8 + 2 * tg;
                *reinterpret_cast<u32*>(&hw[row * HS + col])      = vh;
                *reinterpret_cast<u32*>(&hw[row * HS + 64 + col]) = vl;
            }
        }
        asm volatile("bar.sync %0, %1;" :: "r"(1 + mh), "r"(128) : "memory");

        // ---- projection from NEW h ----
        {
            const __nv_bfloat16* hn = sH + (hp ^ 1) * 32 * HS;
            u32 nh4[4][4], nl4[4][4];
            LD_AFRAGS(nh4, nl4, hn, HS, r0, r1, tg);
            float pacc[4] = {0.f, 0.f, 0.f, 0.f};
#pragma unroll
            for (int ks = 0; ks < 4; ks++) {
                const uint4 w = sPf[(wq * 4 + ks) * 32 + lane];
                MMA(pacc, nh4[ks][0], nh4[ks][1], nh4[ks][2], nh4[ks][3], w.x, w.y);
                MMA(pacc, nl4[ks][0], nl4[ks][1], nl4[ks][2], nl4[ks][3], w.x, w.y);
                MMA(pacc, nh4[ks][0], nh4[ks][1], nh4[ks][2], nh4[ks][3], w.z, w.w);
            }
            const float p00 = pacc[0] + pb0, p01 = pacc[1] + pb1;
            const float p10 = pacc[2] + pb0, p11 = pacc[3] + pb1;
            const int col = 8 * wq + 2 * tg;
            *reinterpret_cast<float2*>(&out[((size_t)(rowbase + r0) * TOUT + t) * C_ + col]) = make_float2(p00, p01);
            *reinterpret_cast<float2*>(&out[((size_t)(rowbase + r1) * TOUT + t) * C_ + col]) = make_float2(p10, p11);
            __nv_bfloat16* pn = sP + (pp ^ 1) * 32 * PS;
            u32 vh, vl;
            split2(p00, p01, vh, vl);
            *reinterpret_cast<u32*>(&pn[r0 * PS + col])      = vh;
            *reinterpret_cast<u32*>(&pn[r0 * PS + 32 + col]) = vl;
            split2(p10, p11, vh, vl);
            *reinterpret_cast<u32*>(&pn[r1 * PS + col])      = vh;
            *reinterpret_cast<u32*>(&pn[r1 * PS + 32 + col]) = vl;
        }
        asm volatile("bar.sync %0, %1;" :: "r"(1 + mh), "r"(128) : "memory");
        hp ^= 1; pp ^= 1;
    }
}

// ============================ launch ============================
extern "C" void kernel_launch(void* const* d_in, const int* in_sizes, int n_in,
                              void* d_out, int out_size)
{
    (void)in_sizes; (void)n_in; (void)out_size;
    const float* x    = (const float*)d_in[0];
    const float* eWih = (const float*)d_in[1];
    const float* eWhh = (const float*)d_in[2];
    const float* eBih = (const float*)d_in[3];
    const float* eBhh = (const float*)d_in[4];
    const float* dWih = (const float*)d_in[5];
    const float* dWhh = (const float*)d_in[6];
    const float* dBih = (const float*)d_in[7];
    const float* dBhh = (const float*)d_in[8];
    const float* pW   = (const float*)d_in[9];
    const float* pB   = (const float*)d_in[10];
    float* out = (float*)d_out;

    xsplit_kernel<<<(TIN * B_) / 128, 256>>>(x);

    cudaFuncSetAttribute(gru_fused,
                         cudaFuncAttributeMaxDynamicSharedMemorySize, SM_TOTAL);
    gru_fused<<<B_ / 32, 256, SM_TOTAL>>>(
        x, eWih, eWhh, eBih, eBhh, dWih, dWhh, dBih, dBhh, pW, pB, out);
}